// round 8
// baseline (speedup 1.0000x reference)
#include <cuda_runtime.h>
#include <cstdint>

// high_order_input: x[4,8,128,128] f32 -> out[4,8,210,16384] f32
// ht2: 45 pairs c_i*c_j (i<=j); ht3: 165 triples c_i*c_j*c_k (i<=j<=k), matching
// reference tpcm2/tpcm3 order (verified rel_err 3.9e-08 across R1-R7).
//
// R8: group-major. One CTA = (plane, (i,j) group, row half). The pair product
// p = c_i*c_j is computed once and reused for the pair term AND all triples
// p*c_k (k=j..8), amortizing loads/window/shifts over up to 10 output streams.
// R7 profiling showed issue=60% (57 instrs per store); this cuts to ~20/store.
// k-loop unrolled with compile-time row pick + shift; stores use compile-time
// immediates from one rebased pointer. Big groups (small j) scheduled first.

#define HWDIM 128
#define LPIX  (HWDIM * HWDIM)   // 16384
#define NTERM 210
#define FULLM 0xffffffffu

__device__ __forceinline__ float4 zero4() { return make_float4(0.f, 0.f, 0.f, 0.f); }

// Horizontal shift of a warp-distributed row (lane L holds cols 4L..4L+3).
// c=0 -> cols w-1 (zero pad), c=1 -> centered, c=2 -> cols w+1 (zero pad).
// c is warp-uniform (constant-folded when called with compile-time c).
__device__ __forceinline__ float4 hshift(float4 v, int c, int lane)
{
    if (c == 1) return v;
    if (c == 0) {
        float pw = __shfl_up_sync(FULLM, v.w, 1);
        return make_float4(lane == 0 ? 0.f : pw, v.x, v.y, v.z);
    }
    float nx = __shfl_down_sync(FULLM, v.x, 1);
    return make_float4(v.y, v.z, v.w, lane == 31 ? 0.f : nx);
}

__global__ __launch_bounds__(256, 5)
void high_order_group_kernel(const float* __restrict__ x, float* __restrict__ out)
{
    // bid = g*64 + plane*2 + half, with groups g ordered j-ascending so the
    // largest groups (j small -> many triples) launch in the first wave.
    const int bid   = blockIdx.x;
    const int g     = bid >> 6;          // 0..44
    const int rem   = bid & 63;
    const int plane = rem >> 1;          // 0..31
    const int half  = rem & 1;

    // Decode g -> (i, j): groups listed j-ascending, i = 0..j within each j.
    int j = 0;
    while ((j + 1) * (j + 2) / 2 <= g) j++;
    const int i = g - j * (j + 1) / 2;

    // Output slot indices in the reference enumeration:
    // t2(i,j) = sum_{i'<i}(9-i') + (j-i); t3base = first triple of prefix (i,j).
    const int t2 = i * (19 - i) / 2 + (j - i);
    int t3b = 45;
    for (int ii = 0; ii < i; ii++) t3b += (9 - ii) * (10 - ii) / 2;
    for (int jj = i; jj < j; jj++) t3b += (9 - jj);

    const int di = i / 3, ci = i % 3;
    const int dj = j / 3, cj = j % 3;

    const int lane = threadIdx.x & 31;
    const int warp = threadIdx.x >> 5;

    const float* __restrict__ xp  = x + (size_t)plane * LPIX;
    float* __restrict__ op2 = out + ((size_t)plane * NTERM + t2) * LPIX;
    // Rebase so triple k stores at op3 + k*LPIX (k >= j only; guarded).
    float* __restrict__ op3 = out + ((size_t)plane * NTERM + (t3b - j)) * LPIX;

    // Warp covers 8 consecutive rows; lane covers cols 4L..4L+3 (one row/iter).
    const int rowbase = half * 64 + warp * 8;
    const int colb    = lane * 4;

    float4 rm = (rowbase > 0)
        ? __ldg(reinterpret_cast<const float4*>(xp + (rowbase - 1) * HWDIM + colb))
        : zero4();
    float4 rc = __ldg(reinterpret_cast<const float4*>(xp + rowbase * HWDIM + colb));

    #pragma unroll
    for (int it = 0; it < 8; it++) {
        const int h = rowbase + it;
        float4 rp = (h < HWDIM - 1)
            ? __ldg(reinterpret_cast<const float4*>(xp + (h + 1) * HWDIM + colb))
            : zero4();

        float4 vi = (di == 0) ? rm : (di == 1) ? rc : rp;   // warp-uniform SELs
        float4 vj = (dj == 0) ? rm : (dj == 1) ? rc : rp;
        vi = hshift(vi, ci, lane);
        vj = hshift(vj, cj, lane);

        float4 p;
        p.x = vi.x * vj.x;
        p.y = vi.y * vj.y;
        p.z = vi.z * vj.z;
        p.w = vi.w * vj.w;

        const int off = h * HWDIM + colb;
        __stcs(reinterpret_cast<float4*>(op2 + off), p);

        // Triples k = j..8, unrolled with compile-time row pick + shift.
        // Guard is warp-uniform (j is CTA-uniform).
        #pragma unroll
        for (int k0 = 0; k0 < 9; k0++) {
            if (k0 >= j) {
                const int dk = k0 / 3, ck = k0 % 3;         // compile-time
                float4 vk = (dk == 0) ? rm : (dk == 1) ? rc : rp;
                vk = hshift(vk, ck, lane);
                float4 r;
                r.x = p.x * vk.x;
                r.y = p.y * vk.y;
                r.z = p.z * vk.z;
                r.w = p.w * vk.w;
                __stcs(reinterpret_cast<float4*>(op3 + (size_t)k0 * LPIX + off), r);
            }
        }

        rm = rc;
        rc = rp;
    }
}

extern "C" void kernel_launch(void* const* d_in, const int* in_sizes, int n_in,
                              void* d_out, int out_size)
{
    const float* x = (const float*)d_in[0];
    float* out = (float*)d_out;
    // tpcm2 (d_in[1]) / tpcm3 (d_in[2]) are compile-time constants for K=3; hardcoded.
    (void)in_sizes; (void)n_in; (void)out_size;

    const int grid = 45 * 32 * 2;   // (i,j) groups x planes x row-halves = 2880
    const int block = 256;          // 8 warps x 8 rows = 64 rows per CTA
    high_order_group_kernel<<<grid, block>>>(x, out);
}

// round 9
// speedup vs baseline: 1.3642x; 1.3642x over previous
#include <cuda_runtime.h>
#include <cstdint>

// high_order_input: x[4,8,128,128] f32 -> out[4,8,210,16384] f32
// ht2: 45 pairs c_i*c_j (i<=j); ht3: 165 triples c_i*c_j*c_k (i<=j<=k), matching
// reference tpcm2/tpcm3 order (verified rel_err 3.9e-08 across R1-R8).
//
// R9: group-major (one CTA = (plane, (i,j), row-half); pair product p reused for
// all triples p*c_k) with j as a COMPILE-TIME template parameter. R8's runtime-j
// predicated k-loop issued ~9 STG.128 per iter with ~half dead -> L1tex 82%,
// 92us. Templating j removes all dead stores and constant-folds every k-side
// row pick and horizontal shift; only the i operand keeps one runtime shift.

#define HWDIM 128
#define LPIX  (HWDIM * HWDIM)   // 16384
#define NTERM 210
#define FULLM 0xffffffffu

__device__ __forceinline__ float4 zero4() { return make_float4(0.f, 0.f, 0.f, 0.f); }

__device__ __forceinline__ float4 ldg4(const float* p)
{
    return __ldg(reinterpret_cast<const float4*>(p));
}

// Horizontal shift of a warp-distributed row (lane L holds cols 4L..4L+3).
// c=0 -> cols w-1 (zero pad), c=1 -> centered, c=2 -> cols w+1 (zero pad).
// When c is a compile-time constant the branches fold away entirely.
__device__ __forceinline__ float4 hshift(float4 v, int c, int lane)
{
    if (c == 1) return v;
    if (c == 0) {
        float pw = __shfl_up_sync(FULLM, v.w, 1);
        return make_float4(lane == 0 ? 0.f : pw, v.x, v.y, v.z);
    }
    float nx = __shfl_down_sync(FULLM, v.x, 1);
    return make_float4(v.y, v.z, v.w, lane == 31 ? 0.f : nx);
}

template <int J>
__device__ __forceinline__ void run_group(const float* __restrict__ xp,
                                          float* __restrict__ op2,
                                          float* __restrict__ op3,
                                          int di, int ci, int lane, int rowbase)
{
    const int colb = lane * 4;

    // Rolling 3-row window: rm = h-1, rc = h, rp = h+1 (zero-padded).
    float4 rm = (rowbase > 0) ? ldg4(xp + (rowbase - 1) * HWDIM + colb) : zero4();
    float4 rc = ldg4(xp + rowbase * HWDIM + colb);

    #pragma unroll 2
    for (int it = 0; it < 8; it++) {
        const int h = rowbase + it;
        float4 rp = (h < HWDIM - 1) ? ldg4(xp + (h + 1) * HWDIM + colb) : zero4();

        // i operand: runtime row pick (uniform SELs) + one runtime shift.
        float4 vi = (di == 0) ? rm : (di == 1) ? rc : rp;
        vi = hshift(vi, ci, lane);

        // j operand: fully compile-time.
        float4 vj = (J / 3 == 0) ? rm : (J / 3 == 1) ? rc : rp;
        vj = hshift(vj, J % 3, lane);

        float4 p;
        p.x = vi.x * vj.x;
        p.y = vi.y * vj.y;
        p.z = vi.z * vj.z;
        p.w = vi.w * vj.w;

        const int off = h * HWDIM + colb;
        __stcs(reinterpret_cast<float4*>(op2 + off), p);

        // Triples k = J..8: compile-time trip count, picks and shifts all fold.
        #pragma unroll
        for (int k0 = J; k0 < 9; k0++) {
            float4 vk = (k0 / 3 == 0) ? rm : (k0 / 3 == 1) ? rc : rp;
            vk = hshift(vk, k0 % 3, lane);
            float4 r;
            r.x = p.x * vk.x;
            r.y = p.y * vk.y;
            r.z = p.z * vk.z;
            r.w = p.w * vk.w;
            __stcs(reinterpret_cast<float4*>(op3 + (size_t)k0 * LPIX + off), r);
        }

        rm = rc;
        rc = rp;
    }
}

__global__ __launch_bounds__(256, 6)
void high_order_group_kernel(const float* __restrict__ x, float* __restrict__ out)
{
    // bid = g*64 + plane*2 + half; groups g ordered j-ascending so the largest
    // groups (small j -> many triples) launch in the first waves.
    const int bid   = blockIdx.x;
    const int g     = bid >> 6;          // 0..44
    const int rem   = bid & 63;
    const int plane = rem >> 1;          // 0..31
    const int half  = rem & 1;

    // Decode g -> (i, j): j-ascending, i = 0..j within each j.
    int j = 0;
    while ((j + 1) * (j + 2) / 2 <= g) j++;
    const int i = g - j * (j + 1) / 2;

    // Output slots in reference order:
    // t2(i,j) = i*(19-i)/2 + (j-i); t3b = first triple with prefix (i,j).
    const int t2 = i * (19 - i) / 2 + (j - i);
    int t3b = 45;
    for (int ii = 0; ii < i; ii++) t3b += (9 - ii) * (10 - ii) / 2;
    for (int jj = i; jj < j; jj++) t3b += (9 - jj);

    const int di = i / 3, ci = i % 3;

    const int lane = threadIdx.x & 31;
    const int warp = threadIdx.x >> 5;
    const int rowbase = half * 64 + warp * 8;   // 8 warps x 8 rows = 64 rows

    const float* __restrict__ xp  = x + (size_t)plane * LPIX;
    float* __restrict__ op2 = out + ((size_t)plane * NTERM + t2) * LPIX;
    float* __restrict__ op3 = out + ((size_t)plane * NTERM + (t3b - j)) * LPIX;

    switch (j) {
        case 0: run_group<0>(xp, op2, op3, di, ci, lane, rowbase); break;
        case 1: run_group<1>(xp, op2, op3, di, ci, lane, rowbase); break;
        case 2: run_group<2>(xp, op2, op3, di, ci, lane, rowbase); break;
        case 3: run_group<3>(xp, op2, op3, di, ci, lane, rowbase); break;
        case 4: run_group<4>(xp, op2, op3, di, ci, lane, rowbase); break;
        case 5: run_group<5>(xp, op2, op3, di, ci, lane, rowbase); break;
        case 6: run_group<6>(xp, op2, op3, di, ci, lane, rowbase); break;
        case 7: run_group<7>(xp, op2, op3, di, ci, lane, rowbase); break;
        case 8: run_group<8>(xp, op2, op3, di, ci, lane, rowbase); break;
    }
}

extern "C" void kernel_launch(void* const* d_in, const int* in_sizes, int n_in,
                              void* d_out, int out_size)
{
    const float* x = (const float*)d_in[0];
    float* out = (float*)d_out;
    // tpcm2 (d_in[1]) / tpcm3 (d_in[2]) are compile-time constants for K=3; hardcoded.
    (void)in_sizes; (void)n_in; (void)out_size;

    const int grid = 45 * 32 * 2;   // (i,j) groups x planes x row-halves = 2880
    const int block = 256;
    high_order_group_kernel<<<grid, block>>>(x, out);
}